// round 8
// baseline (speedup 1.0000x reference)
#include <cuda_runtime.h>
#include <cuda_bf16.h>
#include <cstdint>

#define N_TOT 32768
#define K_TOT 8192
#define DDIM  64
#define ZQ_ELEMS 2097152
#define M_CTA 128
#define NB    64                  // codes per tile (= one chunk)
#define NTILES (K_TOT / NB)       // 128
#define EPS_DOT 6e-5f
#define LIST_CAP (1u << 20)

typedef unsigned long long ull;

// device scratch (no cudaMalloc allowed)
__device__ float g_enorm[K_TOT];
__device__ float g_znorm[N_TOT];
__device__ __align__(16) float g_zt[N_TOT * DDIM];             // 8MB z transposed
__device__ __align__(16) __nv_bfloat16 g_ebf16[K_TOT * DDIM];  // 1MB
__device__ unsigned g_list[LIST_CAP];                          // 4MB survivors
__device__ unsigned g_cnt;
__device__ ull   g_win[N_TOT];
__device__ float g_partial[128];

// ---------------- helpers ----------------
__device__ __forceinline__ uint32_t smem_u32(const void* p) {
    uint32_t a;
    asm("{ .reg .u64 t; cvta.to.shared.u64 t, %1; cvt.u32.u64 %0, t; }"
        : "=r"(a) : "l"(p));
    return a;
}
__device__ __forceinline__ unsigned packbf(float lo, float hi) {
    __nv_bfloat162 t = __floats2bfloat162_rn(lo, hi);
    return *reinterpret_cast<unsigned*>(&t);
}
__device__ __forceinline__ void mma16816(float c[4], const unsigned a[4],
                                         unsigned b0, unsigned b1) {
    asm volatile(
        "mma.sync.aligned.m16n8k16.row.col.f32.bf16.bf16.f32 "
        "{%0,%1,%2,%3}, {%4,%5,%6,%7}, {%8,%9}, {%0,%1,%2,%3};\n"
        : "+f"(c[0]), "+f"(c[1]), "+f"(c[2]), "+f"(c[3])
        : "r"(a[0]), "r"(a[1]), "r"(a[2]), "r"(a[3]), "r"(b0), "r"(b1));
}

// ---------------------------------------------------------------------------
// prep: ||e||^2 exact (reference order) + bf16 copy + zero survivor counter
// ---------------------------------------------------------------------------
__global__ void prep_kernel(const float* __restrict__ emb) {
    if (blockIdx.x == 0 && threadIdx.x == 0) g_cnt = 0;
    int k = blockIdx.x * blockDim.x + threadIdx.x;
    if (k < K_TOT) {
        const float* r = emb + (size_t)k * DDIM;
        __nv_bfloat16* o = g_ebf16 + (size_t)k * DDIM;
        float s = 0.f;
        #pragma unroll
        for (int c = 0; c < DDIM; ++c) {
            float v = r[c];
            s = __fadd_rn(s, __fmul_rn(v, v));
            o[c] = __float2bfloat16(v);
        }
        g_enorm[k] = s;
    }
}

// prep: ||z||^2 exact (sequential c=0..63) + transposed z copy + g_win init
__global__ __launch_bounds__(256) void znorm_kernel(const float* __restrict__ z) {
    __shared__ float zs[DDIM * 64];
    const int tid = threadIdx.x;
    const int n0  = blockIdx.x * 64;
    const int zbase = (n0 >> 12) * 262144 + (n0 & 4095);
    for (int r = tid; r < DDIM * 64; r += 256)
        zs[r] = z[zbase + (r >> 6) * 4096 + (r & 63)];
    __syncthreads();
    if (tid < 64) {
        float s = 0.f;
        #pragma unroll
        for (int c = 0; c < DDIM; ++c) {
            float v = zs[c * 64 + tid];
            s = __fadd_rn(s, __fmul_rn(v, v));
        }
        g_znorm[n0 + tid] = s;
        g_win[n0 + tid] = ~0ull;
    }
    // write z transposed: g_zt[n][d]
    #pragma unroll
    for (int i = 0; i < 16; ++i) {
        int f = tid + 256 * i;          // 4096 values
        int r = f >> 6, d = f & 63;
        g_zt[(size_t)(n0 + r) * DDIM + d] = zs[d * 64 + r];
    }
}

// ---------------------------------------------------------------------------
// Pass A: bf16 mma GEMM + smem chunk maxima + fused rowmax & survivor emit
// grid = 256 CTAs (128 rows) x 256 threads (8 warps x 16 rows)
// dyn smem: [0,16K) B double buffer | [16K, +66048) chunkmax[128][129]
//           (z staging overlaid)    | then rowmax[128]
// ---------------------------------------------------------------------------
__global__ __launch_bounds__(256) void passA_kernel(const float* __restrict__ z) {
    extern __shared__ __align__(16) char smem[];
    uint4* bufs      = (uint4*)smem;                        // 2 x 8KB
    float* chunkmax  = (float*)(smem + 16384);              // [128][129]
    float* rowmaxs   = (float*)(smem + 16384 + 66048);      // [128]
    float* zs        = (float*)(smem + 16384);              // phase-1 overlay

    const int tid  = threadIdx.x;
    const int lane = tid & 31;
    const int w    = tid >> 5;
    const int n0   = blockIdx.x * M_CTA;
    const int zbase = (n0 >> 12) * 262144 + (n0 & 4095);

    // ---- phase 1: stage z transposed [d][r] (coalesced), build A frags ----
    #pragma unroll
    for (int i = 0; i < 32; ++i) {
        int f = tid + 256 * i;
        int d = f >> 7, r = f & 127;
        zs[d * 128 + r] = z[zbase + d * 4096 + r];
    }
    __syncthreads();

    const int g  = lane >> 2;
    const int c2 = (lane & 3) * 2;
    const int rl = 16 * w + g;

    unsigned a[4][4];
    #pragma unroll
    for (int s = 0; s < 4; ++s) {
        int k0 = 16 * s + c2;
        a[s][0] = packbf(zs[k0 * 128 + rl],           zs[(k0 + 1) * 128 + rl]);
        a[s][1] = packbf(zs[k0 * 128 + rl + 8],       zs[(k0 + 1) * 128 + rl + 8]);
        a[s][2] = packbf(zs[(k0 + 8) * 128 + rl],     zs[(k0 + 9) * 128 + rl]);
        a[s][3] = packbf(zs[(k0 + 8) * 128 + rl + 8], zs[(k0 + 9) * 128 + rl + 8]);
    }
    __syncthreads();   // zs region now reused as chunkmax

    const uint32_t bbase = smem_u32(smem);

    // stage tile 0 into buffer 0 (16B-unit XOR swizzle inside code rows)
    {
        const uint4* src = (const uint4*)g_ebf16;
        #pragma unroll
        for (int i = 0; i < 2; ++i) {
            int q = tid + 256 * i;
            int code = q >> 3, j = q & 7;
            bufs[code * 8 + (j ^ (code & 7))] = src[q];
        }
    }
    __syncthreads();

    const int bcode = lane & 7;
    const int bhalf = (lane >> 3) & 1;

    float m0run = -1e30f, m1run = -1e30f;

    for (int t = 0; t < NTILES; ++t) {
        const uint32_t cur = bbase + (t & 1) * 8192;

        if (t + 1 < NTILES) {
            const uint4* src = (const uint4*)(g_ebf16 + (size_t)(t + 1) * NB * DDIM);
            uint4* dst = bufs + ((t + 1) & 1) * 512;
            #pragma unroll
            for (int i = 0; i < 2; ++i) {
                int q = tid + 256 * i;
                int code = q >> 3, j = q & 7;
                dst[code * 8 + (j ^ (code & 7))] = src[q];
            }
        }

        float cf[8][4];
        #pragma unroll
        for (int nt = 0; nt < 8; ++nt) {
            cf[nt][0] = cf[nt][1] = cf[nt][2] = cf[nt][3] = 0.f;
            #pragma unroll
            for (int s = 0; s < 4; ++s) {
                int code = 8 * nt + bcode;
                int j = 2 * s + bhalf;
                uint32_t addr = cur + code * 128 + (j ^ (code & 7)) * 16;
                unsigned b0, b1;
                asm volatile("ldmatrix.sync.aligned.m8n8.x2.shared.b16 {%0,%1}, [%2];"
                             : "=r"(b0), "=r"(b1) : "r"(addr));
                mma16816(cf[nt], a[s], b0, b1);
            }
        }

        // epilogue: max over the 64 codes of this tile (= chunk t)
        float m0 = fmaxf(cf[0][0], cf[0][1]), m1 = fmaxf(cf[0][2], cf[0][3]);
        #pragma unroll
        for (int nt = 1; nt < 8; ++nt) {
            m0 = fmaxf(m0, fmaxf(cf[nt][0], cf[nt][1]));
            m1 = fmaxf(m1, fmaxf(cf[nt][2], cf[nt][3]));
        }
        m0 = fmaxf(m0, __shfl_xor_sync(~0u, m0, 1));
        m0 = fmaxf(m0, __shfl_xor_sync(~0u, m0, 2));
        m1 = fmaxf(m1, __shfl_xor_sync(~0u, m1, 1));
        m1 = fmaxf(m1, __shfl_xor_sync(~0u, m1, 2));
        m0run = fmaxf(m0run, m0);
        m1run = fmaxf(m1run, m1);
        if ((lane & 3) == 0) {
            chunkmax[rl * 129 + t] = m0;
            chunkmax[(rl + 8) * 129 + t] = m1;
        }

        __syncthreads();
    }

    // rowmax + survivor scan (all in smem), emit compact global list
    if ((lane & 3) == 0) {
        rowmaxs[rl] = m0run;
        rowmaxs[rl + 8] = m1run;
    }
    __syncthreads();

    {
        const int r = tid >> 1;                 // 2 threads per row
        const int cb = (tid & 1) * 64;
        const float th = rowmaxs[r] - EPS_DOT;
        const float* cmr = chunkmax + r * 129 + cb;
        const unsigned tag = (unsigned)(n0 + r) << 7;
        #pragma unroll 8
        for (int c = 0; c < 64; ++c) {
            if (cmr[c] >= th) {
                unsigned pos = atomicAdd(&g_cnt, 1u);
                if (pos < LIST_CAP) g_list[pos] = tag | (cb + c);
            }
        }
    }
}

// ---------------------------------------------------------------------------
// Pass B: persistent warps over survivor list; exact rescore of one 64-code
// chunk per entry (bit-exact reference chain); atomicMin winner key.
// ---------------------------------------------------------------------------
__global__ __launch_bounds__(256) void passB_kernel(const float* __restrict__ emb) {
    const int lane = threadIdx.x & 31;
    const unsigned nwarps = (gridDim.x * 256) >> 5;
    const unsigned gw = (blockIdx.x * 256 + threadIdx.x) >> 5;
    const unsigned cnt = min(g_cnt, LIST_CAP);

    for (unsigned i = gw; i < cnt; i += nwarps) {
        const unsigned e = g_list[i];
        const int row = e >> 7;
        const int chunk = e & 127;
        const float zn = g_znorm[row];
        const float4* zt = (const float4*)(g_zt + (size_t)row * DDIM);

        float4 zq[16];
        #pragma unroll
        for (int j = 0; j < 16; ++j) zq[j] = zt[j];   // warp-uniform, L1 bcast

        ull best = ~0ull;
        #pragma unroll
        for (int h = 0; h < 2; ++h) {
            int k = chunk * 64 + lane + 32 * h;
            const float4* er = (const float4*)(emb + (size_t)k * DDIM);
            float s = 0.f;
            #pragma unroll
            for (int d4 = 0; d4 < 16; ++d4) {
                float4 ev = er[d4];
                s = __fmaf_rn(zq[d4].x, ev.x, s);
                s = __fmaf_rn(zq[d4].y, ev.y, s);
                s = __fmaf_rn(zq[d4].z, ev.z, s);
                s = __fmaf_rn(zq[d4].w, ev.w, s);
            }
            float d = __fsub_rn(__fadd_rn(zn, g_enorm[k]), __fmul_rn(2.f, s));
            ull key = ((ull)__float_as_uint(d) << 32) | (unsigned)k;
            if (key < best) best = key;
        }
        #pragma unroll
        for (int o = 16; o > 0; o >>= 1) {
            ull o2 = __shfl_xor_sync(~0u, best, o);
            if (o2 < best) best = o2;
        }
        if (lane == 0) atomicMin(&g_win[row], best);
    }
}

// ---------------------------------------------------------------------------
// gather: z_q = fl(z + fl(zq - z)) (exact reference ops), loss partials, idx
// ---------------------------------------------------------------------------
__global__ __launch_bounds__(256) void gather_kernel(
    const float* __restrict__ z, const float* __restrict__ emb,
    float* __restrict__ out, int out_size)
{
    const int n = blockIdx.x * 256 + threadIdx.x;
    const int idx = (int)(g_win[n] & 0xFFFFFFFFull);
    const int obase = (n >> 12) * 262144 + (n & 4095);

    const float4* er = (const float4*)(emb + (size_t)idx * DDIM);
    float acc = 0.f;
    #pragma unroll
    for (int i = 0; i < DDIM / 4; ++i) {
        float4 e4 = er[i];
        float ev[4] = {e4.x, e4.y, e4.z, e4.w};
        #pragma unroll
        for (int c = 0; c < 4; ++c) {
            int d = 4 * i + c;
            float zv = z[obase + d * 4096];
            float df = __fsub_rn(ev[c], zv);
            out[obase + d * 4096] = __fadd_rn(zv, df);
            acc = fmaf(df, df, acc);
        }
    }
    if (out_size >= ZQ_ELEMS + 1 + N_TOT)
        out[ZQ_ELEMS + 1 + n] = (float)idx;

    __shared__ float red[256];
    red[threadIdx.x] = acc;
    __syncthreads();
    #pragma unroll
    for (int s = 128; s > 0; s >>= 1) {
        if (threadIdx.x < s) red[threadIdx.x] += red[threadIdx.x + s];
        __syncthreads();
    }
    if (threadIdx.x == 0) g_partial[blockIdx.x] = red[0];
}

__global__ void loss_kernel(float* __restrict__ out, int out_size) {
    __shared__ float red[128];
    red[threadIdx.x] = g_partial[threadIdx.x];
    __syncthreads();
    #pragma unroll
    for (int s = 64; s > 0; s >>= 1) {
        if (threadIdx.x < s) red[threadIdx.x] += red[threadIdx.x + s];
        __syncthreads();
    }
    if (threadIdx.x == 0 && out_size >= ZQ_ELEMS + 1) {
        float m = red[0] / (float)ZQ_ELEMS;
        out[ZQ_ELEMS] = __fadd_rn(m, __fmul_rn(0.25f, m));
    }
}

// ---------------------------------------------------------------------------
extern "C" void kernel_launch(void* const* d_in, const int* in_sizes, int n_in,
                              void* d_out, int out_size) {
    const float* z   = (const float*)d_in[0];
    const float* emb = (const float*)d_in[1];
    float* out = (float*)d_out;

    const int SMEM_A = 16384 + 66048 + 512;   // 82944 B
    static int smem_set = 0;
    if (!smem_set) {
        cudaFuncSetAttribute(passA_kernel,
            cudaFuncAttributeMaxDynamicSharedMemorySize, SMEM_A);
        smem_set = 1;
    }

    prep_kernel<<<K_TOT / 256, 256>>>(emb);
    znorm_kernel<<<N_TOT / 64, 256>>>(z);
    passA_kernel<<<N_TOT / M_CTA, 256, SMEM_A>>>(z);
    passB_kernel<<<512, 256>>>(emb);
    gather_kernel<<<N_TOT / 256, 256>>>(z, emb, out, out_size);
    loss_kernel<<<1, 128>>>(out, out_size);
}

// round 9
// speedup vs baseline: 1.4516x; 1.4516x over previous
#include <cuda_runtime.h>
#include <cuda_bf16.h>
#include <cstdint>

#define N_TOT 32768
#define K_TOT 8192
#define DDIM  64
#define ZQ_ELEMS 2097152
#define M_CTA 128
#define NB    64                  // codes per tile
#define NTILES (K_TOT / NB)       // 128
#define EPS_DOT 6e-5f
#define LIST_CAP (1u << 20)
#define SLIST_CAP 4096

typedef unsigned long long ull;

// device scratch (no cudaMalloc allowed)
__device__ float g_enorm[K_TOT];
__device__ float g_znorm[N_TOT];
__device__ __align__(16) float g_zt[N_TOT * DDIM];             // 8MB z transposed
__device__ __align__(16) __nv_bfloat16 g_ebf16[K_TOT * DDIM];  // 1MB
__device__ unsigned g_list[LIST_CAP];                          // survivors (row<<13|k)
__device__ unsigned g_cnt;
__device__ ull   g_win[N_TOT];
__device__ float g_partial[128];

// ---------------- helpers ----------------
__device__ __forceinline__ uint32_t smem_u32(const void* p) {
    uint32_t a;
    asm("{ .reg .u64 t; cvta.to.shared.u64 t, %1; cvt.u32.u64 %0, t; }"
        : "=r"(a) : "l"(p));
    return a;
}
__device__ __forceinline__ unsigned packbf(float lo, float hi) {
    __nv_bfloat162 t = __floats2bfloat162_rn(lo, hi);
    return *reinterpret_cast<unsigned*>(&t);
}
__device__ __forceinline__ void mma16816(float c[4], const unsigned a[4],
                                         unsigned b0, unsigned b1) {
    asm volatile(
        "mma.sync.aligned.m16n8k16.row.col.f32.bf16.bf16.f32 "
        "{%0,%1,%2,%3}, {%4,%5,%6,%7}, {%8,%9}, {%0,%1,%2,%3};\n"
        : "+f"(c[0]), "+f"(c[1]), "+f"(c[2]), "+f"(c[3])
        : "r"(a[0]), "r"(a[1]), "r"(a[2]), "r"(a[3]), "r"(b0), "r"(b1));
}

// ---------------------------------------------------------------------------
// prep: ||e||^2 exact (reference order) + bf16 copy + zero survivor counter
// ---------------------------------------------------------------------------
__global__ void prep_kernel(const float* __restrict__ emb) {
    if (blockIdx.x == 0 && threadIdx.x == 0) g_cnt = 0;
    int k = blockIdx.x * blockDim.x + threadIdx.x;
    if (k < K_TOT) {
        const float* r = emb + (size_t)k * DDIM;
        __nv_bfloat16* o = g_ebf16 + (size_t)k * DDIM;
        float s = 0.f;
        #pragma unroll
        for (int c = 0; c < DDIM; ++c) {
            float v = r[c];
            s = __fadd_rn(s, __fmul_rn(v, v));
            o[c] = __float2bfloat16(v);
        }
        g_enorm[k] = s;
    }
}

// prep: ||z||^2 exact (sequential c=0..63) + transposed z copy + g_win init
__global__ __launch_bounds__(256) void znorm_kernel(const float* __restrict__ z) {
    __shared__ float zs[DDIM * 64];
    const int tid = threadIdx.x;
    const int n0  = blockIdx.x * 64;
    const int zbase = (n0 >> 12) * 262144 + (n0 & 4095);
    for (int r = tid; r < DDIM * 64; r += 256)
        zs[r] = z[zbase + (r >> 6) * 4096 + (r & 63)];
    __syncthreads();
    if (tid < 64) {
        float s = 0.f;
        #pragma unroll
        for (int c = 0; c < DDIM; ++c) {
            float v = zs[c * 64 + tid];
            s = __fadd_rn(s, __fmul_rn(v, v));
        }
        g_znorm[n0 + tid] = s;
        g_win[n0 + tid] = ~0ull;
    }
    #pragma unroll
    for (int i = 0; i < 16; ++i) {
        int f = tid + 256 * i;
        int r = f >> 6, d = f & 63;
        g_zt[(size_t)(n0 + r) * DDIM + d] = zs[d * 64 + r];
    }
}

// ---------------------------------------------------------------------------
// Pass A: bf16 mma GEMM, running rowmax, inline per-code survivor emission
// grid = 256 CTAs (128 rows) x 256 threads (8 warps x 16 rows)
// dyn smem 48KB: [0,16K) B double buffer | [16K,48K) z staging (phase 1 only)
// ---------------------------------------------------------------------------
__global__ __launch_bounds__(256) void passA_kernel(const float* __restrict__ z) {
    extern __shared__ __align__(16) char smem[];
    uint4* bufs = (uint4*)smem;                 // 2 x 8KB
    float* zs   = (float*)(smem + 16384);       // 32KB, phase 1 only
    __shared__ unsigned s_cnt, s_base;
    __shared__ unsigned s_list[SLIST_CAP];

    const int tid  = threadIdx.x;
    const int lane = tid & 31;
    const int w    = tid >> 5;
    const int n0   = blockIdx.x * M_CTA;
    const int zbase = (n0 >> 12) * 262144 + (n0 & 4095);

    if (tid == 0) s_cnt = 0;

    // ---- phase 1: stage z transposed [d][r] (coalesced), build A frags ----
    #pragma unroll
    for (int i = 0; i < 32; ++i) {
        int f = tid + 256 * i;
        int d = f >> 7, r = f & 127;
        zs[d * 128 + r] = z[zbase + d * 4096 + r];
    }
    __syncthreads();

    const int g  = lane >> 2;
    const int c2 = (lane & 3) * 2;
    const int rl = 16 * w + g;

    unsigned a[4][4];
    #pragma unroll
    for (int s = 0; s < 4; ++s) {
        int k0 = 16 * s + c2;
        a[s][0] = packbf(zs[k0 * 128 + rl],           zs[(k0 + 1) * 128 + rl]);
        a[s][1] = packbf(zs[k0 * 128 + rl + 8],       zs[(k0 + 1) * 128 + rl + 8]);
        a[s][2] = packbf(zs[(k0 + 8) * 128 + rl],     zs[(k0 + 9) * 128 + rl]);
        a[s][3] = packbf(zs[(k0 + 8) * 128 + rl + 8], zs[(k0 + 9) * 128 + rl + 8]);
    }
    __syncthreads();

    const uint32_t bbase = smem_u32(smem);

    // stage tile 0 into buffer 0 (16B-unit XOR swizzle inside code rows)
    {
        const uint4* src = (const uint4*)g_ebf16;
        #pragma unroll
        for (int i = 0; i < 2; ++i) {
            int q = tid + 256 * i;
            int code = q >> 3, j = q & 7;
            bufs[code * 8 + (j ^ (code & 7))] = src[q];
        }
    }
    __syncthreads();

    const int bcode = lane & 7;
    const int bhalf = (lane >> 3) & 1;
    const unsigned row0 = n0 + rl;          // rows for c[0..1] / c[2..3]=+8

    float m0run = -1e30f, m1run = -1e30f;

    for (int t = 0; t < NTILES; ++t) {
        const uint32_t cur = bbase + (t & 1) * 8192;

        if (t + 1 < NTILES) {
            const uint4* src = (const uint4*)(g_ebf16 + (size_t)(t + 1) * NB * DDIM);
            uint4* dst = bufs + ((t + 1) & 1) * 512;
            #pragma unroll
            for (int i = 0; i < 2; ++i) {
                int q = tid + 256 * i;
                int code = q >> 3, j = q & 7;
                dst[code * 8 + (j ^ (code & 7))] = src[q];
            }
        }

        float cf[8][4];
        #pragma unroll
        for (int nt = 0; nt < 8; ++nt) {
            cf[nt][0] = cf[nt][1] = cf[nt][2] = cf[nt][3] = 0.f;
            #pragma unroll
            for (int s = 0; s < 4; ++s) {
                int code = 8 * nt + bcode;
                int j = 2 * s + bhalf;
                uint32_t addr = cur + code * 128 + (j ^ (code & 7)) * 16;
                unsigned b0, b1;
                asm volatile("ldmatrix.sync.aligned.m8n8.x2.shared.b16 {%0,%1}, [%2];"
                             : "=r"(b0), "=r"(b1) : "r"(addr));
                mma16816(cf[nt], a[s], b0, b1);
            }
        }

        // per-thread local maxima, then 4-lane-group chunk max
        float l0 = fmaxf(cf[0][0], cf[0][1]), l1 = fmaxf(cf[0][2], cf[0][3]);
        #pragma unroll
        for (int nt = 1; nt < 8; ++nt) {
            l0 = fmaxf(l0, fmaxf(cf[nt][0], cf[nt][1]));
            l1 = fmaxf(l1, fmaxf(cf[nt][2], cf[nt][3]));
        }
        float m0 = fmaxf(l0, __shfl_xor_sync(~0u, l0, 1));
        m0 = fmaxf(m0, __shfl_xor_sync(~0u, m0, 2));
        float m1 = fmaxf(l1, __shfl_xor_sync(~0u, l1, 1));
        m1 = fmaxf(m1, __shfl_xor_sync(~0u, m1, 2));
        m0run = fmaxf(m0run, m0);
        m1run = fmaxf(m1run, m1);

        // rare emission: any of this thread's codes within EPS of running max
        const float th0 = m0run - EPS_DOT;
        const float th1 = m1run - EPS_DOT;
        if (l0 >= th0) {
            #pragma unroll
            for (int nt = 0; nt < 8; ++nt)
                #pragma unroll
                for (int q = 0; q < 2; ++q)
                    if (cf[nt][q] >= th0) {
                        unsigned k = t * 64 + nt * 8 + c2 + q;
                        unsigned p = atomicAdd(&s_cnt, 1u);
                        if (p < SLIST_CAP) s_list[p] = (row0 << 13) | k;
                    }
        }
        if (l1 >= th1) {
            #pragma unroll
            for (int nt = 0; nt < 8; ++nt)
                #pragma unroll
                for (int q = 0; q < 2; ++q)
                    if (cf[nt][2 + q] >= th1) {
                        unsigned k = t * 64 + nt * 8 + c2 + q;
                        unsigned p = atomicAdd(&s_cnt, 1u);
                        if (p < SLIST_CAP) s_list[p] = ((row0 + 8) << 13) | k;
                    }
        }

        __syncthreads();
    }

    // flush CTA survivor list with one global atomic
    unsigned nloc = min(s_cnt, (unsigned)SLIST_CAP);
    if (tid == 0) s_base = atomicAdd(&g_cnt, nloc);
    __syncthreads();
    for (unsigned i = tid; i < nloc; i += 256) {
        unsigned p = s_base + i;
        if (p < LIST_CAP) g_list[p] = s_list[i];
    }
}

// ---------------------------------------------------------------------------
// Pass B: one thread per survivor (row,k); bit-exact sequential fp32 chain;
// atomicMin winner key (min d, ties -> lowest k)
// ---------------------------------------------------------------------------
__global__ __launch_bounds__(256) void passB_kernel(const float* __restrict__ emb) {
    const unsigned cnt = min(g_cnt, (unsigned)LIST_CAP);
    const unsigned stride = gridDim.x * 256;
    for (unsigned i = blockIdx.x * 256 + threadIdx.x; i < cnt; i += stride) {
        const unsigned e = g_list[i];
        const int row = e >> 13;
        const int k   = e & 8191;
        const float zn = g_znorm[row];
        const float4* zr = (const float4*)(g_zt + (size_t)row * DDIM);
        const float4* er = (const float4*)(emb + (size_t)k * DDIM);
        float s = 0.f;
        #pragma unroll
        for (int d4 = 0; d4 < 16; ++d4) {
            float4 a = zr[d4];
            float4 b = er[d4];
            s = __fmaf_rn(a.x, b.x, s);
            s = __fmaf_rn(a.y, b.y, s);
            s = __fmaf_rn(a.z, b.z, s);
            s = __fmaf_rn(a.w, b.w, s);
        }
        float d = __fsub_rn(__fadd_rn(zn, g_enorm[k]), __fmul_rn(2.f, s));
        ull key = ((ull)__float_as_uint(d) << 32) | (unsigned)k;
        atomicMin(&g_win[row], key);
    }
}

// ---------------------------------------------------------------------------
// gather: z_q = fl(z + fl(zq - z)) (exact reference ops), loss partials, idx
// ---------------------------------------------------------------------------
__global__ __launch_bounds__(256) void gather_kernel(
    const float* __restrict__ z, const float* __restrict__ emb,
    float* __restrict__ out, int out_size)
{
    const int n = blockIdx.x * 256 + threadIdx.x;
    const int idx = (int)(g_win[n] & 8191u);
    const int obase = (n >> 12) * 262144 + (n & 4095);

    const float4* er = (const float4*)(emb + (size_t)idx * DDIM);
    float acc = 0.f;
    #pragma unroll
    for (int i = 0; i < DDIM / 4; ++i) {
        float4 e4 = er[i];
        float ev[4] = {e4.x, e4.y, e4.z, e4.w};
        #pragma unroll
        for (int c = 0; c < 4; ++c) {
            int d = 4 * i + c;
            float zv = z[obase + d * 4096];
            float df = __fsub_rn(ev[c], zv);
            out[obase + d * 4096] = __fadd_rn(zv, df);
            acc = fmaf(df, df, acc);
        }
    }
    if (out_size >= ZQ_ELEMS + 1 + N_TOT)
        out[ZQ_ELEMS + 1 + n] = (float)idx;

    __shared__ float red[256];
    red[threadIdx.x] = acc;
    __syncthreads();
    #pragma unroll
    for (int s = 128; s > 0; s >>= 1) {
        if (threadIdx.x < s) red[threadIdx.x] += red[threadIdx.x + s];
        __syncthreads();
    }
    if (threadIdx.x == 0) g_partial[blockIdx.x] = red[0];
}

__global__ void loss_kernel(float* __restrict__ out, int out_size) {
    __shared__ float red[128];
    red[threadIdx.x] = g_partial[threadIdx.x];
    __syncthreads();
    #pragma unroll
    for (int s = 64; s > 0; s >>= 1) {
        if (threadIdx.x < s) red[threadIdx.x] += red[threadIdx.x + s];
        __syncthreads();
    }
    if (threadIdx.x == 0 && out_size >= ZQ_ELEMS + 1) {
        float m = red[0] / (float)ZQ_ELEMS;
        out[ZQ_ELEMS] = __fadd_rn(m, __fmul_rn(0.25f, m));
    }
}

// ---------------------------------------------------------------------------
extern "C" void kernel_launch(void* const* d_in, const int* in_sizes, int n_in,
                              void* d_out, int out_size) {
    const float* z   = (const float*)d_in[0];
    const float* emb = (const float*)d_in[1];
    float* out = (float*)d_out;

    const int SMEM_A = 49152;   // 16KB B bufs + 32KB z staging
    static int smem_set = 0;
    if (!smem_set) {
        cudaFuncSetAttribute(passA_kernel,
            cudaFuncAttributeMaxDynamicSharedMemorySize, SMEM_A);
        smem_set = 1;
    }

    prep_kernel<<<K_TOT / 256, 256>>>(emb);
    znorm_kernel<<<N_TOT / 64, 256>>>(z);
    passA_kernel<<<N_TOT / M_CTA, 256, SMEM_A>>>(z);
    passB_kernel<<<256, 256>>>(emb);
    gather_kernel<<<N_TOT / 256, 256>>>(z, emb, out, out_size);
    loss_kernel<<<1, 128>>>(out, out_size);
}

// round 10
// speedup vs baseline: 1.6809x; 1.1580x over previous
#include <cuda_runtime.h>
#include <cuda_bf16.h>
#include <cstdint>

#define N_TOT 32768
#define K_TOT 8192
#define DDIM  64
#define ZQ_ELEMS 2097152
#define M_CTA 128
#define NB    64                  // codes per tile
#define NTILES (K_TOT / NB)       // 128
#define EPS_DOT 6e-5f
#define LIST_CAP (1u << 20)
#define CAND_CAP 4096

typedef unsigned long long ull;

// device scratch (no cudaMalloc allowed)
__device__ float g_enorm[K_TOT];
__device__ float g_znorm[N_TOT];
__device__ __align__(16) float g_zt[N_TOT * DDIM];             // 8MB z transposed
__device__ __align__(16) __nv_bfloat16 g_ebf16[K_TOT * DDIM];  // 1MB
__device__ unsigned g_list[LIST_CAP];                          // survivors (row<<13|k)
__device__ unsigned g_cnt;
__device__ ull   g_win[N_TOT];
__device__ float g_partial[128];

// ---------------- helpers ----------------
__device__ __forceinline__ uint32_t smem_u32(const void* p) {
    uint32_t a;
    asm("{ .reg .u64 t; cvta.to.shared.u64 t, %1; cvt.u32.u64 %0, t; }"
        : "=r"(a) : "l"(p));
    return a;
}
__device__ __forceinline__ unsigned packbf(float lo, float hi) {
    __nv_bfloat162 t = __floats2bfloat162_rn(lo, hi);
    return *reinterpret_cast<unsigned*>(&t);
}
__device__ __forceinline__ void mma16816(float c[4], const unsigned a[4],
                                         unsigned b0, unsigned b1) {
    asm volatile(
        "mma.sync.aligned.m16n8k16.row.col.f32.bf16.bf16.f32 "
        "{%0,%1,%2,%3}, {%4,%5,%6,%7}, {%8,%9}, {%0,%1,%2,%3};\n"
        : "+f"(c[0]), "+f"(c[1]), "+f"(c[2]), "+f"(c[3])
        : "r"(a[0]), "r"(a[1]), "r"(a[2]), "r"(a[3]), "r"(b0), "r"(b1));
}

// ---------------------------------------------------------------------------
// prep: ||e||^2 exact (reference order) + bf16 copy + zero survivor counter
// ---------------------------------------------------------------------------
__global__ void prep_kernel(const float* __restrict__ emb) {
    if (blockIdx.x == 0 && threadIdx.x == 0) g_cnt = 0;
    int k = blockIdx.x * blockDim.x + threadIdx.x;
    if (k < K_TOT) {
        const float* r = emb + (size_t)k * DDIM;
        __nv_bfloat16* o = g_ebf16 + (size_t)k * DDIM;
        float s = 0.f;
        #pragma unroll
        for (int c = 0; c < DDIM; ++c) {
            float v = r[c];
            s = __fadd_rn(s, __fmul_rn(v, v));
            o[c] = __float2bfloat16(v);
        }
        g_enorm[k] = s;
    }
}

// prep: ||z||^2 exact (sequential c=0..63) + transposed z copy + g_win init
__global__ __launch_bounds__(256) void znorm_kernel(const float* __restrict__ z) {
    __shared__ float zs[DDIM * 64];
    const int tid = threadIdx.x;
    const int n0  = blockIdx.x * 64;
    const int zbase = (n0 >> 12) * 262144 + (n0 & 4095);
    for (int r = tid; r < DDIM * 64; r += 256)
        zs[r] = z[zbase + (r >> 6) * 4096 + (r & 63)];
    __syncthreads();
    if (tid < 64) {
        float s = 0.f;
        #pragma unroll
        for (int c = 0; c < DDIM; ++c) {
            float v = zs[c * 64 + tid];
            s = __fadd_rn(s, __fmul_rn(v, v));
        }
        g_znorm[n0 + tid] = s;
        g_win[n0 + tid] = ~0ull;
    }
    #pragma unroll
    for (int i = 0; i < 16; ++i) {
        int f = tid + 256 * i;
        int r = f >> 6, d = f & 63;
        g_zt[(size_t)(n0 + r) * DDIM + d] = zs[d * 64 + r];
    }
}

// ---------------------------------------------------------------------------
// Pass A: bf16 mma GEMM, running rowmax, candidate emission (tag+value) into
// smem, final-rowmax refilter, compact global flush.
// grid = 256 CTAs (128 rows) x 256 threads (8 warps x 16 rows)
// dyn smem 48KB: [0,16K) B double buffer
//                [16K,48K) phase 1: z staging | mainloop: cand tag/val arrays
// ---------------------------------------------------------------------------
__global__ __launch_bounds__(256) void passA_kernel(const float* __restrict__ z) {
    extern __shared__ __align__(16) char smem[];
    uint4*    bufs     = (uint4*)smem;                     // 2 x 8KB
    float*    zs       = (float*)(smem + 16384);           // 32KB, phase 1 only
    unsigned* cand_tag = (unsigned*)(smem + 16384);        // 16KB (4096)
    float*    cand_val = (float*)(smem + 16384 + 16384);   // 16KB (4096)
    __shared__ unsigned s_cnt;
    __shared__ float rowmaxs[M_CTA];

    const int tid  = threadIdx.x;
    const int lane = tid & 31;
    const int w    = tid >> 5;
    const int n0   = blockIdx.x * M_CTA;
    const int zbase = (n0 >> 12) * 262144 + (n0 & 4095);

    if (tid == 0) s_cnt = 0;

    // ---- phase 1: stage z transposed [d][r] (coalesced), build A frags ----
    #pragma unroll
    for (int i = 0; i < 32; ++i) {
        int f = tid + 256 * i;
        int d = f >> 7, r = f & 127;
        zs[d * 128 + r] = z[zbase + d * 4096 + r];
    }
    __syncthreads();

    const int g  = lane >> 2;
    const int c2 = (lane & 3) * 2;
    const int rl = 16 * w + g;

    unsigned a[4][4];
    #pragma unroll
    for (int s = 0; s < 4; ++s) {
        int k0 = 16 * s + c2;
        a[s][0] = packbf(zs[k0 * 128 + rl],           zs[(k0 + 1) * 128 + rl]);
        a[s][1] = packbf(zs[k0 * 128 + rl + 8],       zs[(k0 + 1) * 128 + rl + 8]);
        a[s][2] = packbf(zs[(k0 + 8) * 128 + rl],     zs[(k0 + 9) * 128 + rl]);
        a[s][3] = packbf(zs[(k0 + 8) * 128 + rl + 8], zs[(k0 + 9) * 128 + rl + 8]);
    }
    __syncthreads();   // z staging region becomes candidate arrays

    const uint32_t bbase = smem_u32(smem);

    // stage tile 0 into buffer 0 (16B-unit XOR swizzle inside code rows)
    {
        const uint4* src = (const uint4*)g_ebf16;
        #pragma unroll
        for (int i = 0; i < 2; ++i) {
            int q = tid + 256 * i;
            int code = q >> 3, j = q & 7;
            bufs[code * 8 + (j ^ (code & 7))] = src[q];
        }
    }
    __syncthreads();

    const int bcode = lane & 7;
    const int bhalf = (lane >> 3) & 1;
    const unsigned row0 = n0 + rl;          // rows for cf[.][0..1] / [2..3]=+8

    float m0run = -1e30f, m1run = -1e30f;

    for (int t = 0; t < NTILES; ++t) {
        const uint32_t cur = bbase + (t & 1) * 8192;

        if (t + 1 < NTILES) {
            const uint4* src = (const uint4*)(g_ebf16 + (size_t)(t + 1) * NB * DDIM);
            uint4* dst = bufs + ((t + 1) & 1) * 512;
            #pragma unroll
            for (int i = 0; i < 2; ++i) {
                int q = tid + 256 * i;
                int code = q >> 3, j = q & 7;
                dst[code * 8 + (j ^ (code & 7))] = src[q];
            }
        }

        float cf[8][4];
        #pragma unroll
        for (int nt = 0; nt < 8; ++nt) {
            cf[nt][0] = cf[nt][1] = cf[nt][2] = cf[nt][3] = 0.f;
            #pragma unroll
            for (int s = 0; s < 4; ++s) {
                int code = 8 * nt + bcode;
                int j = 2 * s + bhalf;
                uint32_t addr = cur + code * 128 + (j ^ (code & 7)) * 16;
                unsigned b0, b1;
                asm volatile("ldmatrix.sync.aligned.m8n8.x2.shared.b16 {%0,%1}, [%2];"
                             : "=r"(b0), "=r"(b1) : "r"(addr));
                mma16816(cf[nt], a[s], b0, b1);
            }
        }

        // per-thread local maxima, then 4-lane-group row max
        float l0 = fmaxf(cf[0][0], cf[0][1]), l1 = fmaxf(cf[0][2], cf[0][3]);
        #pragma unroll
        for (int nt = 1; nt < 8; ++nt) {
            l0 = fmaxf(l0, fmaxf(cf[nt][0], cf[nt][1]));
            l1 = fmaxf(l1, fmaxf(cf[nt][2], cf[nt][3]));
        }
        float m0 = fmaxf(l0, __shfl_xor_sync(~0u, l0, 1));
        m0 = fmaxf(m0, __shfl_xor_sync(~0u, m0, 2));
        float m1 = fmaxf(l1, __shfl_xor_sync(~0u, l1, 1));
        m1 = fmaxf(m1, __shfl_xor_sync(~0u, m1, 2));
        m0run = fmaxf(m0run, m0);
        m1run = fmaxf(m1run, m1);

        // rare: emit candidates vs running rowmax (superset of final survivors)
        const float th0 = m0run - EPS_DOT;
        const float th1 = m1run - EPS_DOT;
        if (l0 >= th0) {
            #pragma unroll
            for (int nt = 0; nt < 8; ++nt)
                #pragma unroll
                for (int q = 0; q < 2; ++q)
                    if (cf[nt][q] >= th0) {
                        unsigned k = t * 64 + nt * 8 + c2 + q;
                        unsigned p = atomicAdd(&s_cnt, 1u);
                        if (p < CAND_CAP) {
                            cand_tag[p] = (row0 << 13) | k;
                            cand_val[p] = cf[nt][q];
                        }
                    }
        }
        if (l1 >= th1) {
            #pragma unroll
            for (int nt = 0; nt < 8; ++nt)
                #pragma unroll
                for (int q = 0; q < 2; ++q)
                    if (cf[nt][2 + q] >= th1) {
                        unsigned k = t * 64 + nt * 8 + c2 + q;
                        unsigned p = atomicAdd(&s_cnt, 1u);
                        if (p < CAND_CAP) {
                            cand_tag[p] = ((row0 + 8) << 13) | k;
                            cand_val[p] = cf[nt][2 + q];
                        }
                    }
        }

        __syncthreads();
    }

    // final per-row maxima, then refilter candidates and flush survivors
    if ((lane & 3) == 0) {
        rowmaxs[rl] = m0run;
        rowmaxs[rl + 8] = m1run;
    }
    __syncthreads();

    {
        const unsigned nloc = min(s_cnt, (unsigned)CAND_CAP);
        for (unsigned i = tid; i < nloc; i += 256) {
            unsigned tag = cand_tag[i];
            int rloc = (int)(tag >> 13) - n0;
            if (cand_val[i] >= rowmaxs[rloc] - EPS_DOT) {
                unsigned p = atomicAdd(&g_cnt, 1u);
                if (p < LIST_CAP) g_list[p] = tag;
            }
        }
    }
}

// ---------------------------------------------------------------------------
// Pass B: one thread per survivor (row,k); bit-exact sequential fp32 chain;
// atomicMin winner key (min d, ties -> lowest k)
// ---------------------------------------------------------------------------
__global__ __launch_bounds__(256) void passB_kernel(const float* __restrict__ emb) {
    const unsigned cnt = min(g_cnt, (unsigned)LIST_CAP);
    const unsigned stride = gridDim.x * 256;
    for (unsigned i = blockIdx.x * 256 + threadIdx.x; i < cnt; i += stride) {
        const unsigned e = g_list[i];
        const int row = e >> 13;
        const int k   = e & 8191;
        const float zn = g_znorm[row];
        const float4* zr = (const float4*)(g_zt + (size_t)row * DDIM);
        const float4* er = (const float4*)(emb + (size_t)k * DDIM);
        float s = 0.f;
        #pragma unroll
        for (int d4 = 0; d4 < 16; ++d4) {
            float4 av = zr[d4];
            float4 bv = er[d4];
            s = __fmaf_rn(av.x, bv.x, s);
            s = __fmaf_rn(av.y, bv.y, s);
            s = __fmaf_rn(av.z, bv.z, s);
            s = __fmaf_rn(av.w, bv.w, s);
        }
        float d = __fsub_rn(__fadd_rn(zn, g_enorm[k]), __fmul_rn(2.f, s));
        ull key = ((ull)__float_as_uint(d) << 32) | (unsigned)k;
        atomicMin(&g_win[row], key);
    }
}

// ---------------------------------------------------------------------------
// gather: z_q = fl(z + fl(zq - z)) (exact reference ops), loss partials, idx
// ---------------------------------------------------------------------------
__global__ __launch_bounds__(256) void gather_kernel(
    const float* __restrict__ z, const float* __restrict__ emb,
    float* __restrict__ out, int out_size)
{
    const int n = blockIdx.x * 256 + threadIdx.x;
    const int idx = (int)(g_win[n] & 8191u);
    const int obase = (n >> 12) * 262144 + (n & 4095);

    const float4* er = (const float4*)(emb + (size_t)idx * DDIM);
    float acc = 0.f;
    #pragma unroll
    for (int i = 0; i < DDIM / 4; ++i) {
        float4 e4 = er[i];
        float ev[4] = {e4.x, e4.y, e4.z, e4.w};
        #pragma unroll
        for (int c = 0; c < 4; ++c) {
            int d = 4 * i + c;
            float zv = z[obase + d * 4096];
            float df = __fsub_rn(ev[c], zv);
            out[obase + d * 4096] = __fadd_rn(zv, df);
            acc = fmaf(df, df, acc);
        }
    }
    if (out_size >= ZQ_ELEMS + 1 + N_TOT)
        out[ZQ_ELEMS + 1 + n] = (float)idx;

    __shared__ float red[256];
    red[threadIdx.x] = acc;
    __syncthreads();
    #pragma unroll
    for (int s = 128; s > 0; s >>= 1) {
        if (threadIdx.x < s) red[threadIdx.x] += red[threadIdx.x + s];
        __syncthreads();
    }
    if (threadIdx.x == 0) g_partial[blockIdx.x] = red[0];
}

__global__ void loss_kernel(float* __restrict__ out, int out_size) {
    __shared__ float red[128];
    red[threadIdx.x] = g_partial[threadIdx.x];
    __syncthreads();
    #pragma unroll
    for (int s = 64; s > 0; s >>= 1) {
        if (threadIdx.x < s) red[threadIdx.x] += red[threadIdx.x + s];
        __syncthreads();
    }
    if (threadIdx.x == 0 && out_size >= ZQ_ELEMS + 1) {
        float m = red[0] / (float)ZQ_ELEMS;
        out[ZQ_ELEMS] = __fadd_rn(m, __fmul_rn(0.25f, m));
    }
}

// ---------------------------------------------------------------------------
extern "C" void kernel_launch(void* const* d_in, const int* in_sizes, int n_in,
                              void* d_out, int out_size) {
    const float* z   = (const float*)d_in[0];
    const float* emb = (const float*)d_in[1];
    float* out = (float*)d_out;

    const int SMEM_A = 49152;   // 16KB B bufs + 32KB staging/candidates
    static int smem_set = 0;
    if (!smem_set) {
        cudaFuncSetAttribute(passA_kernel,
            cudaFuncAttributeMaxDynamicSharedMemorySize, SMEM_A);
        smem_set = 1;
    }

    prep_kernel<<<K_TOT / 256, 256>>>(emb);
    znorm_kernel<<<N_TOT / 64, 256>>>(z);
    passA_kernel<<<N_TOT / M_CTA, 256, SMEM_A>>>(z);
    passB_kernel<<<128, 256>>>(emb);
    gather_kernel<<<N_TOT / 256, 256>>>(z, emb, out, out_size);
    loss_kernel<<<1, 128>>>(out, out_size);
}